// round 17
// baseline (speedup 1.0000x reference)
#include <cuda_runtime.h>
#include <cuda_fp16.h>
#include <math.h>
#include <stdint.h>

#define Bk 4
#define Tk 2048
#define Ck 1024
#define Hk 16
#define HSk 64
#define EPSk 1e-5f
#define MROWS (Bk*Tk)
#define N3 (3*Ck)
#define FF (4*Ck)

/* scratch (device globals; allocation is forbidden) */
__device__ __half g_h1[MROWS*Ck];
__device__ __half g_qkv[(size_t)MROWS*N3];
__device__ __half g_att[MROWS*Ck];
__device__ float  g_x2[MROWS*Ck];
__device__ __half g_h2[MROWS*Ck];
__device__ __half g_ffn[(size_t)MROWS*FF];
__device__ __half g_wpack[(size_t)N3*Ck];
__device__ float  g_bpack[N3];
__device__ __half g_woT[Ck*Ck];
__device__ __half g_w1T[(size_t)FF*Ck];
__device__ __half g_w2T[(size_t)Ck*FF];

/* ---------------- helpers ---------------- */
__device__ __forceinline__ void cp_async16(void* s, const void* g) {
    unsigned sa = (unsigned)__cvta_generic_to_shared(s);
    asm volatile("cp.async.cg.shared.global [%0], [%1], 16;" :: "r"(sa), "l"(g));
}
__device__ __forceinline__ void cp_commit() { asm volatile("cp.async.commit_group;"); }
__device__ __forceinline__ void cp_wait1() { asm volatile("cp.async.wait_group 1;" ::: "memory"); }

__device__ __forceinline__ uint32_t smem_u32(const void* p) {
    return (uint32_t)__cvta_generic_to_shared(p);
}
__device__ __forceinline__ void mma16816(float* c, const unsigned* a, const unsigned* b) {
    asm volatile("mma.sync.aligned.m16n8k16.row.col.f32.f16.f16.f32 {%0,%1,%2,%3}, {%4,%5,%6,%7}, {%8,%9}, {%0,%1,%2,%3};"
        : "+f"(c[0]), "+f"(c[1]), "+f"(c[2]), "+f"(c[3])
        : "r"(a[0]), "r"(a[1]), "r"(a[2]), "r"(a[3]), "r"(b[0]), "r"(b[1]));
}
__device__ __forceinline__ void ldsm4(unsigned* r, uint32_t addr) {
    asm volatile("ldmatrix.sync.aligned.m8n8.x4.shared.b16 {%0,%1,%2,%3}, [%4];"
        : "=r"(r[0]), "=r"(r[1]), "=r"(r[2]), "=r"(r[3]) : "r"(addr));
}
__device__ __forceinline__ void ldsm4t(unsigned* r, uint32_t addr) {
    asm volatile("ldmatrix.sync.aligned.m8n8.x4.trans.shared.b16 {%0,%1,%2,%3}, [%4];"
        : "=r"(r[0]), "=r"(r[1]), "=r"(r[2]), "=r"(r[3]) : "r"(addr));
}

/* ---------------- LayerNorm over time axis, emits half --------------------- */
__global__ void ln_time_kernel(const float* __restrict__ x,
                               const float* __restrict__ gam,
                               const float* __restrict__ beta,
                               __half* __restrict__ out) {
    int cb = blockIdx.x % (Ck/32);
    int b  = blockIdx.x / (Ck/32);
    int tx = threadIdx.x, ty = threadIdx.y;
    int c  = cb*32 + tx;
    const float* xp = x + (size_t)b*Tk*Ck + c;
    float s = 0.f, s2 = 0.f;
    for (int t = ty; t < Tk; t += 8) {
        float v = xp[(size_t)t*Ck];
        s += v;
        s2 += v*v;
    }
    __shared__ float ss[8][32];
    __shared__ float ss2[8][32];
    ss[ty][tx] = s;
    ss2[ty][tx] = s2;
    __syncthreads();
    if (ty == 0) {
        for (int i = 1; i < 8; i++) { s += ss[i][tx]; s2 += ss2[i][tx]; }
        float m   = s / (float)Tk;
        float var = (s2 - (float)Tk*m*m) / (float)(Tk-1);
        float inv = rsqrtf(var + EPSk);
        ss[0][tx]  = m;
        ss2[0][tx] = inv;
    }
    __syncthreads();
    float m = ss[0][tx], inv = ss2[0][tx];
    float gg = gam[c], bb = beta[c];
    __half* op = out + (size_t)b*Tk*Ck + c;
    for (int t = ty; t < Tk; t += 8) {
        op[(size_t)t*Ck] = __float2half_rn(gg * (xp[(size_t)t*Ck] - m) * inv + bb);
    }
}

/* ---------------- pack qkv weights: K-major [3072][1024] half -------------- */
__global__ void pack_qkvT_kernel(const float* __restrict__ Wq, const float* __restrict__ Wk,
                                 const float* __restrict__ Wv, const float* __restrict__ bq,
                                 const float* __restrict__ bkk, const float* __restrict__ bv) {
    int i = blockIdx.x * blockDim.x + threadIdx.x;
    if (i < N3*Ck) {
        int n = i >> 10;
        int c = i & 1023;
        int which = n >> 10;
        int nl = n & 1023;
        int h = nl >> 6;
        int d = nl & 63;
        const float* W = (which == 0) ? Wq : ((which == 1) ? Wk : Wv);
        g_wpack[(size_t)n*Ck + c] = __float2half_rn(W[((size_t)h*Ck + c)*HSk + d]);
    }
    if (i < Ck) {
        g_bpack[i]        = bq[i];
        g_bpack[Ck + i]   = bkk[i];
        g_bpack[2*Ck + i] = bv[i];
    }
}

/* ---------------- tiled transpose: dst[n][k] = half(src[k][n]) ------------- */
__global__ void transpose_h_kernel(const float* __restrict__ src, __half* __restrict__ dst,
                                   int K, int N) {
    __shared__ float t[32][33];
    int k0 = blockIdx.y*32, n0 = blockIdx.x*32;
    int tx = threadIdx.x, ty = threadIdx.y;
    for (int i = 0; i < 4; i++) {
        t[ty + 8*i][tx] = src[(size_t)(k0 + ty + 8*i)*N + n0 + tx];
    }
    __syncthreads();
    for (int i = 0; i < 4; i++) {
        dst[(size_t)(n0 + ty + 8*i)*K + k0 + tx] = __float2half_rn(t[tx][ty + 8*i]);
    }
}

/* ---------------- fp16 tensor GEMM: C = A[M,K] x Bt[N,K]^T ----------------- */
/* 128x128 block, 4 warps (64x64 warp tiles), BK=64 stages, 3-stage ring.     */
/* One barrier per 64-K stage; load issued after barrier (ring depth 3).      */
#define GP 72
#define GSTG (128*GP)
#define G_SMEM (3*2*GSTG*2)

template<bool RELU, bool RES, bool OHALF>
__global__ __launch_bounds__(128, 2)
void hgemm_kernel(int M, int N, int K,
                  const __half* __restrict__ A,
                  const __half* __restrict__ Bt,
                  const float* __restrict__ bias,
                  const float* __restrict__ res,
                  float* __restrict__ Cf,
                  __half* __restrict__ Ch) {
    extern __shared__ __half smh[];
    int tid  = threadIdx.x;
    int lane = tid & 31;
    int warp = tid >> 5;
    int g = lane >> 2;
    int c = lane & 3;
    int warpM = warp & 1;
    int warpN = warp >> 1;
    int bm0 = blockIdx.y * 128;
    int bn0 = blockIdx.x * 128;

    float acc[4][8][4];
    for (int mt = 0; mt < 4; mt++) {
        for (int nt = 0; nt < 8; nt++) {
            acc[mt][nt][0] = 0.f; acc[mt][nt][1] = 0.f;
            acc[mt][nt][2] = 0.f; acc[mt][nt][3] = 0.f;
        }
    }

    const __half* Ag = A  + (size_t)bm0 * K;
    const __half* Bg = Bt + (size_t)bn0 * K;
    int nk = K / 64;

    auto load_stage = [&](int st, int buf) {
        __half* As = smh + buf*2*GSTG;
        __half* Bs = As + GSTG;
        int k0 = st * 64;
        for (int i = 0; i < 8; i++) {
            int id = i*128 + tid;
            int row = id >> 3;
            int c8 = id & 7;
            cp_async16(As + row*GP + c8*8, Ag + (size_t)row*K + k0 + c8*8);
        }
        for (int i = 0; i < 8; i++) {
            int id = i*128 + tid;
            int row = id >> 3;
            int c8 = id & 7;
            cp_async16(Bs + row*GP + c8*8, Bg + (size_t)row*K + k0 + c8*8);
        }
    };

    load_stage(0, 0); cp_commit();
    load_stage(1, 1); cp_commit();

    int la = lane & 15;
    int lko = (lane >> 4) * 8;
    int lnb = (lane & 7) + ((lane & 16) >> 1);
    int lkb = lane & 8;

    for (int t = 0; t < nk; t++) {
        cp_wait1();
        __syncthreads();
        if (t + 2 < nk) { load_stage(t + 2, (t + 2) % 3); }
        cp_commit();
        const __half* As = smh + (t % 3)*2*GSTG;
        const __half* Bs = As + GSTG;
        for (int ks = 0; ks < 4; ks++) {
            int kc = ks * 16;
            unsigned af[4][4], bf[8][2];
            for (int mt = 0; mt < 4; mt++) {
                int r0 = warpM*64 + mt*16;
                ldsm4(af[mt], smem_u32(&As[(r0 + la)*GP + kc + lko]));
            }
            for (int pr = 0; pr < 4; pr++) {
                int n0 = warpN*64 + pr*16;
                unsigned rr[4];
                ldsm4(rr, smem_u32(&Bs[(n0 + lnb)*GP + kc + lkb]));
                bf[pr*2][0] = rr[0]; bf[pr*2][1] = rr[1];
                bf[pr*2+1][0] = rr[2]; bf[pr*2+1][1] = rr[3];
            }
            for (int mt = 0; mt < 4; mt++) {
                for (int nt = 0; nt < 8; nt++) {
                    mma16816(acc[mt][nt], af[mt], bf[nt]);
                }
            }
        }
    }

    for (int mt = 0; mt < 4; mt++) {
        for (int nt = 0; nt < 8; nt++) {
            for (int hh = 0; hh < 2; hh++) {
                int row = bm0 + warpM*64 + mt*16 + g + hh*8;
                int col = bn0 + warpN*64 + nt*8 + 2*c;
                float v0 = acc[mt][nt][hh*2+0] + bias[col];
                float v1 = acc[mt][nt][hh*2+1] + bias[col+1];
                if (RES) {
                    v0 += res[(size_t)row*N + col];
                    v1 += res[(size_t)row*N + col + 1];
                }
                if (RELU) { v0 = fmaxf(v0, 0.f); v1 = fmaxf(v1, 0.f); }
                if (OHALF) {
                    *(__half2*)&Ch[(size_t)row*N + col] = __floats2half2_rn(v0, v1);
                } else {
                    *(float2*)&Cf[(size_t)row*N + col] = make_float2(v0, v1);
                }
            }
        }
    }
}

/* ---------------- flash attention: 128-row Q tile, cp.async KV ring -------- */
/* softmax carried in exp2 domain: scores pre-scaled by 0.03125*log2(e).      */
#define FP 72
#define FA_SMEM ((128*FP + 3*128*FP) * 2)
#define FSCL 0.045084439571429034f   /* 0.03125 * 1.4426950408889634 */

__global__ __launch_bounds__(256, 2)
void flash_h_kernel(const __half* __restrict__ qkv, __half* __restrict__ att) {
    extern __shared__ __half smh[];
    __half* Qs = smh;
    __half* KV = smh + 128*FP;
    __half* Ps = Qs;

    int tid  = threadIdx.x;
    int lane = tid & 31;
    int warp = tid >> 5;
    int gq = lane >> 2;
    int cq = lane & 3;

    const int ntiles = Tk / 128;
    int qt = (ntiles - 1) - (blockIdx.x % ntiles);
    int h  = (blockIdx.x / ntiles) % Hk;
    int b  =  blockIdx.x / (ntiles * Hk);
    int q0 = qt * 128;
    const __half* qbase = qkv + (size_t)b*Tk*N3 + h*HSk;
    const __half* kbase = qbase + Ck;
    const __half* vbase = qbase + 2*Ck;

    for (int i = 0; i < 4; i++) {
        int id = i*256 + tid;
        int r = id >> 3;
        int c8 = id & 7;
        *(uint4*)&Qs[r*FP + c8*8] = *(const uint4*)(qbase + (size_t)(q0 + r)*N3 + c8*8);
    }
    __syncthreads();

    int la = lane & 15;
    int lko = (lane >> 4) * 8;
    int lnb = (lane & 7) + ((lane & 16) >> 1);
    int lkb = lane & 8;
    int ldo = (lane & 16) >> 1;

    int rl = warp*16 + gq;
    unsigned qa[4][4];
    for (int ks = 0; ks < 4; ks++) {
        ldsm4(qa[ks], smem_u32(&Qs[(warp*16 + la)*FP + ks*16 + lko]));
    }
    __syncthreads();

    float m0 = -1e30f, m1 = -1e30f, l0 = 0.f, l1 = 0.f;
    float o[8][4];
    for (int nt = 0; nt < 8; nt++) {
        o[nt][0] = 0.f; o[nt][1] = 0.f; o[nt][2] = 0.f; o[nt][3] = 0.f;
    }

    int row0 = q0 + rl;
    int row1 = row0 + 8;
    int nkb = q0/64 + 2;

    auto stage_kv = [&](int kb, int buf) {
        __half* Kb = KV + buf*128*FP;
        __half* Vb = Kb + 64*FP;
        for (int i = 0; i < 2; i++) {
            int id = i*256 + tid;
            int r = id >> 3;
            int c8 = id & 7;
            cp_async16(&Kb[r*FP + c8*8], kbase + (size_t)(kb*64 + r)*N3 + c8*8);
            cp_async16(&Vb[r*FP + c8*8], vbase + (size_t)(kb*64 + r)*N3 + c8*8);
        }
    };

    stage_kv(0, 0); cp_commit();

    for (int kb = 0; kb < nkb; kb++) {
        if (kb + 1 < nkb) { stage_kv(kb + 1, (kb + 1) % 3); }
        cp_commit();
        cp_wait1();
        __syncthreads();
        const __half* Kb = KV + (kb % 3)*128*FP;
        const __half* Vb = Kb + 64*FP;

        float s[8][4];
        for (int nt = 0; nt < 8; nt++) {
            s[nt][0] = 0.f; s[nt][1] = 0.f; s[nt][2] = 0.f; s[nt][3] = 0.f;
        }
        for (int ks = 0; ks < 4; ks++) {
            int kc = ks*16;
            unsigned bf[8][2];
            for (int pr = 0; pr < 4; pr++) {
                unsigned rr[4];
                ldsm4(rr, smem_u32(&Kb[(pr*16 + lnb)*FP + kc + lkb]));
                bf[pr*2][0] = rr[0]; bf[pr*2][1] = rr[1];
                bf[pr*2+1][0] = rr[2]; bf[pr*2+1][1] = rr[3];
            }
            for (int nt = 0; nt < 8; nt++) {
                mma16816(s[nt], qa[ks], bf[nt]);
            }
        }

        float rmax0 = -1e30f, rmax1 = -1e30f;
        if (kb*64 + 63 <= row0) {
            for (int nt = 0; nt < 8; nt++) {
                s[nt][0] *= FSCL; s[nt][1] *= FSCL;
                s[nt][2] *= FSCL; s[nt][3] *= FSCL;
                rmax0 = fmaxf(rmax0, fmaxf(s[nt][0], s[nt][1]));
                rmax1 = fmaxf(rmax1, fmaxf(s[nt][2], s[nt][3]));
            }
        } else {
            for (int nt = 0; nt < 8; nt++) {
                int col = kb*64 + nt*8 + 2*cq;
                s[nt][0] = (col   <= row0) ? s[nt][0]*FSCL : -1e30f;
                s[nt][1] = (col+1 <= row0) ? s[nt][1]*FSCL : -1e30f;
                s[nt][2] = (col   <= row1) ? s[nt][2]*FSCL : -1e30f;
                s[nt][3] = (col+1 <= row1) ? s[nt][3]*FSCL : -1e30f;
                rmax0 = fmaxf(rmax0, fmaxf(s[nt][0], s[nt][1]));
                rmax1 = fmaxf(rmax1, fmaxf(s[nt][2], s[nt][3]));
            }
        }
        rmax0 = fmaxf(rmax0, __shfl_xor_sync(0xffffffffu, rmax0, 1));
        rmax0 = fmaxf(rmax0, __shfl_xor_sync(0xffffffffu, rmax0, 2));
        rmax1 = fmaxf(rmax1, __shfl_xor_sync(0xffffffffu, rmax1, 1));
        rmax1 = fmaxf(rmax1, __shfl_xor_sync(0xffffffffu, rmax1, 2));
        float mn0 = fmaxf(m0, rmax0);
        float mn1 = fmaxf(m1, rmax1);
        float corr0 = exp2f(m0 - mn0);
        float corr1 = exp2f(m1 - mn1);
        float ps0 = 0.f, ps1 = 0.f;
        for (int nt = 0; nt < 8; nt++) {
            float p0 = exp2f(s[nt][0] - mn0);
            float p1 = exp2f(s[nt][1] - mn0);
            float p2 = exp2f(s[nt][2] - mn1);
            float p3 = exp2f(s[nt][3] - mn1);
            ps0 += p0 + p1;
            ps1 += p2 + p3;
            int cl = nt*8 + 2*cq;
            *(__half2*)&Ps[rl*FP + cl]     = __floats2half2_rn(p0, p1);
            *(__half2*)&Ps[(rl+8)*FP + cl] = __floats2half2_rn(p2, p3);
        }
        ps0 += __shfl_xor_sync(0xffffffffu, ps0, 1);
        ps0 += __shfl_xor_sync(0xffffffffu, ps0, 2);
        ps1 += __shfl_xor_sync(0xffffffffu, ps1, 1);
        ps1 += __shfl_xor_sync(0xffffffffu, ps1, 2);
        l0 = l0*corr0 + ps0;
        l1 = l1*corr1 + ps1;
        m0 = mn0;
        m1 = mn1;
        for (int nt = 0; nt < 8; nt++) {
            o[nt][0] *= corr0; o[nt][1] *= corr0;
            o[nt][2] *= corr1; o[nt][3] *= corr1;
        }
        __syncwarp();

        for (int ks = 0; ks < 4; ks++) {
            int kc = ks*16;
            unsigned pa[4];
            ldsm4(pa, smem_u32(&Ps[(warp*16 + la)*FP + kc + lko]));
            for (int pr = 0; pr < 4; pr++) {
                unsigned rr[4];
                ldsm4t(rr, smem_u32(&Vb[(kc + la)*FP + pr*16 + ldo]));
                mma16816(o[pr*2],     pa, rr + 0);
                mma16816(o[pr*2 + 1], pa, rr + 2);
            }
        }
    }

    float inv0 = 1.f / l0;
    float inv1 = 1.f / l1;
    __half* ob0 = att + (size_t)(b*Tk + row0)*Ck + h*HSk;
    __half* ob1 = att + (size_t)(b*Tk + row1)*Ck + h*HSk;
    for (int nt = 0; nt < 8; nt++) {
        int cl = nt*8 + 2*cq;
        *(__half2*)&ob0[cl] = __floats2half2_rn(o[nt][0]*inv0, o[nt][1]*inv0);
        *(__half2*)&ob1[cl] = __floats2half2_rn(o[nt][2]*inv1, o[nt][3]*inv1);
    }
}

/* --------------------------------------------------------------------------- */
extern "C" void kernel_launch(void* const* d_in, const int* in_sizes, int n_in,
                              void* d_out, int out_size) {
    const float* x     = (const float*)d_in[0];
    const float* ln1_g = (const float*)d_in[1];
    const float* ln1_b = (const float*)d_in[2];
    const float* ln2_g = (const float*)d_in[3];
    const float* ln2_b = (const float*)d_in[4];
    const float* Wq    = (const float*)d_in[5];
    const float* bq    = (const float*)d_in[6];
    const float* Wk    = (const float*)d_in[7];
    const float* bk    = (const float*)d_in[8];
    const float* Wv    = (const float*)d_in[9];
    const float* bv    = (const float*)d_in[10];
    const float* Wo    = (const float*)d_in[11];
    const float* bo    = (const float*)d_in[12];
    const float* W1    = (const float*)d_in[13];
    const float* b1    = (const float*)d_in[14];
    const float* W2    = (const float*)d_in[15];
    const float* b2    = (const float*)d_in[16];
    float* out = (float*)d_out;

    __half *h1, *qkv, *att, *h2, *ffn, *wpack, *woT, *w1T, *w2T;
    float *x2, *bpack;
    cudaGetSymbolAddress((void**)&h1,    g_h1);
    cudaGetSymbolAddress((void**)&qkv,   g_qkv);
    cudaGetSymbolAddress((void**)&att,   g_att);
    cudaGetSymbolAddress((void**)&x2,    g_x2);
    cudaGetSymbolAddress((void**)&h2,    g_h2);
    cudaGetSymbolAddress((void**)&ffn,   g_ffn);
    cudaGetSymbolAddress((void**)&wpack, g_wpack);
    cudaGetSymbolAddress((void**)&bpack, g_bpack);
    cudaGetSymbolAddress((void**)&woT,   g_woT);
    cudaGetSymbolAddress((void**)&w1T,   g_w1T);
    cudaGetSymbolAddress((void**)&w2T,   g_w2T);

    cudaFuncSetAttribute(hgemm_kernel<false,false,true>,  cudaFuncAttributeMaxDynamicSharedMemorySize, G_SMEM);
    cudaFuncSetAttribute(hgemm_kernel<false,true,false>,  cudaFuncAttributeMaxDynamicSharedMemorySize, G_SMEM);
    cudaFuncSetAttribute(hgemm_kernel<true,false,true>,   cudaFuncAttributeMaxDynamicSharedMemorySize, G_SMEM);
    cudaFuncSetAttribute(flash_h_kernel, cudaFuncAttributeMaxDynamicSharedMemorySize, FA_SMEM);

    pack_qkvT_kernel<<<(N3*Ck + 255)/256, 256>>>(Wq, Wk, Wv, bq, bk, bv);
    dim3 tb(32, 8);
    transpose_h_kernel<<<dim3(Ck/32, Ck/32), tb>>>(Wo, woT, Ck, Ck);
    transpose_h_kernel<<<dim3(FF/32, Ck/32), tb>>>(W1, w1T, Ck, FF);
    transpose_h_kernel<<<dim3(Ck/32, FF/32), tb>>>(W2, w2T, FF, Ck);

    dim3 lnb2(32, 8);
    ln_time_kernel<<<Bk*(Ck/32), lnb2>>>(x, ln1_g, ln1_b, h1);

    hgemm_kernel<false,false,true><<<dim3(N3/128, MROWS/128), 128, G_SMEM>>>(
        MROWS, N3, Ck, h1, wpack, bpack, (const float*)0, (float*)0, qkv);

    flash_h_kernel<<<Bk*Hk*(Tk/128), 256, FA_SMEM>>>(qkv, att);

    hgemm_kernel<false,true,false><<<dim3(Ck/128, MROWS/128), 128, G_SMEM>>>(
        MROWS, Ck, Ck, att, woT, bo, x, x2, (__half*)0);

    ln_time_kernel<<<Bk*(Ck/32), lnb2>>>(x2, ln2_g, ln2_b, h2);

    hgemm_kernel<true,false,true><<<dim3(FF/128, MROWS/128), 128, G_SMEM>>>(
        MROWS, FF, Ck, h2, w1T, b1, (const float*)0, (float*)0, ffn);

    hgemm_kernel<false,true,false><<<dim3(Ck/128, MROWS/128), 128, G_SMEM>>>(
        MROWS, Ck, FF, ffn, w2T, b2, x2, out, (__half*)0);
}